// round 14
// baseline (speedup 1.0000x reference)
#include <cuda_runtime.h>
#include <cuda_fp16.h>
#include <cstdint>

#define NROWS 16384
#define CDIM  128
#define FDIM  768
#define HDIM  768
#define NDOM  8
#define KCOLS 16

#define TM   128
#define TN   128
#define TKC  64
#define NTHR 128
#define NCHUNK (FDIM / TKC)     // 12
#define NSLICE (HDIM / TN)      // 6
#define NRT   32                // provisioned row tiles per domain (32*128=4096 rows)

// ---------------- scratch ----------------
__device__ int    g_cnt[NDOM];
__device__ int    g_cur0[NDOM];          // zero-based scatter cursor
__device__ int    g_perm[NROWS];
__device__ float  g_conf[NROWS * 3];
__device__ __half g_f[(size_t)NROWS * FDIM];                   // feats fp16
__device__ __half g_w1t[(size_t)NDOM * HDIM * FDIM];           // W1^T fp16 [d][n][k]
__device__ float  g_dz[(size_t)NSLICE * NROWS * KCOLS];        // partial dz per col-slice

// ---------------- helpers ----------------
__device__ __forceinline__ uint32_t smem_u32(const void* p) {
    uint32_t a;
    asm("{ .reg .u64 t; cvta.to.shared.u64 t, %1; cvt.u32.u64 %0, t; }" : "=r"(a) : "l"(p));
    return a;
}
#define SWZ128(bo) ((bo) ^ (((bo) >> 3) & 0x70))

__device__ __forceinline__ void cp16(uint32_t dst, const void* src, uint32_t sz) {
    asm volatile("cp.async.cg.shared.global [%0], [%1], 16, %2;"
                 :: "r"(dst), "l"(src), "r"(sz) : "memory");
}
#define CP_COMMIT() asm volatile("cp.async.commit_group;" ::: "memory")
#define CP_WAIT(n)  asm volatile("cp.async.wait_group %0;" :: "n"(n) : "memory")

__device__ __forceinline__ void ldx4(uint32_t r[4], uint32_t addr) {
    asm volatile("ldmatrix.sync.aligned.m8n8.x4.shared.b16 {%0,%1,%2,%3}, [%4];"
                 : "=r"(r[0]), "=r"(r[1]), "=r"(r[2]), "=r"(r[3]) : "r"(addr));
}
__device__ __forceinline__ void mma16816(float c[4], const uint32_t a[4],
                                         uint32_t b0, uint32_t b1) {
    asm volatile("mma.sync.aligned.m16n8k16.row.col.f32.f16.f16.f32 "
                 "{%0,%1,%2,%3}, {%4,%5,%6,%7}, {%8,%9}, {%0,%1,%2,%3};"
                 : "+f"(c[0]), "+f"(c[1]), "+f"(c[2]), "+f"(c[3])
                 : "r"(a[0]), "r"(a[1]), "r"(a[2]), "r"(a[3]), "r"(b0), "r"(b1));
}

// ---------------- SMEM layout (gemm1): 2 stages ----------------
#define S_PERM  0            // 128 ints
#define S_CNT   512          // 8 ints
#define S_TILE  1024
#define S_STAGE 32768        // A 16KB + B 16KB
#define S_A     0
#define S_B     16384
// epilogue reuse: tails [4][128] @S_TILE (2048B), W2s [128][17] @+2048 (8704B),
//                 dzbuf [2][128][16] @+12288 (16384B)
#define S_W2S   (S_TILE + 2048)
#define S_DZB   (S_TILE + 12288)
#define SMEM_SZ (1024 + 2 * 32768)   // 66560 -> 3 CTAs/SM

// ---------------- k_zero ----------------
__global__ void k_zero() {
    if (threadIdx.x < NDOM) { g_cnt[threadIdx.x] = 0; g_cur0[threadIdx.x] = 0; }
}

// ---------------- k_prep: cvt feats | transpose W1 | conf+count ----------------
#define NB_CVT  (NROWS * FDIM / 4 / 256)            // 12288
#define NB_W1T  ((FDIM / 32) * (HDIM / 32) * NDOM)  // 4608
#define NB_CONF (NROWS / 256)                       // 64

__global__ void k_prep(const float* __restrict__ feats, const float* __restrict__ W1,
                       const float* __restrict__ z, const int* __restrict__ dom,
                       const int* __restrict__ cols) {
    int b = blockIdx.x;
    int tid = threadIdx.x;
    if (b < NB_CVT) {
        int i = b * 256 + tid;
        float4 v = ((const float4*)feats)[i];
        __half2* dst = (__half2*)g_f;
        dst[i * 2 + 0] = __floats2half2_rn(v.x, v.y);
        dst[i * 2 + 1] = __floats2half2_rn(v.z, v.w);
    } else if (b < NB_CVT + NB_W1T) {
        __shared__ float t[32][33];
        int bi = b - NB_CVT;
        int d = bi / ((FDIM / 32) * (HDIM / 32));
        int rem = bi % ((FDIM / 32) * (HDIM / 32));
        int k0 = (rem / (HDIM / 32)) * 32, n0 = (rem % (HDIM / 32)) * 32;
        int tx = tid & 31, ty = tid >> 5;
        const float* src = W1 + (size_t)d * (FDIM + 3) * HDIM;
#pragma unroll
        for (int r = 0; r < 4; r++)
            t[ty + 8 * r][tx] = src[(size_t)(k0 + ty + 8 * r) * HDIM + n0 + tx];
        __syncthreads();
#pragma unroll
        for (int r = 0; r < 4; r++) {
            size_t o = ((size_t)d * HDIM + n0 + ty + 8 * r) * FDIM + k0 + tx;
            g_w1t[o] = __float2half_rn(t[tx][ty + 8 * r]);
        }
    } else {
        __shared__ int scnt[NDOM];
        int n = (b - NB_CVT - NB_W1T) * 256 + tid;
        if (tid < NDOM) scnt[tid] = 0;
        __syncthreads();
        int d = dom[n];
        atomicAdd(&scnt[d], 1);
        float v[KCOLS];
#pragma unroll
        for (int i = 0; i < KCOLS; i++) v[i] = z[(size_t)n * CDIM + cols[d * KCOLS + i]];
        float m = v[0];
#pragma unroll
        for (int i = 1; i < KCOLS; i++) m = fmaxf(m, v[i]);
        float e[KCOLS], s = 0.f;
#pragma unroll
        for (int i = 0; i < KCOLS; i++) { e[i] = expf(v[i] - m); s += e[i]; }
        float t1 = -1e30f, t2 = -1e30f;
#pragma unroll
        for (int i = 0; i < KCOLS; i++) {
            float x = v[i];
            if (x > t1) { t2 = t1; t1 = x; } else if (x > t2) { t2 = x; }
        }
        float inv = 1.f / s;
        float p1 = expf(t1 - m) * inv, p2 = expf(t2 - m) * inv;
        float logZ = logf(s), ent = 0.f;
#pragma unroll
        for (int i = 0; i < KCOLS; i++) { float pi = e[i] * inv; ent -= pi * (v[i] - m - logZ); }
        ent *= (1.f / logf((float)KCOLS));
        g_conf[n * 3 + 0] = p1;
        g_conf[n * 3 + 1] = p1 - p2;
        g_conf[n * 3 + 2] = ent;
        __syncthreads();
        if (tid < NDOM && scnt[tid] > 0) atomicAdd(&g_cnt[tid], scnt[tid]);
    }
}

// ---------------- scatter ----------------
__global__ void k_scatter(const int* __restrict__ dom) {
    __shared__ int lcnt[NDOM], lbase[NDOM], soff[NDOM];
    int tid = threadIdx.x;
    int n = blockIdx.x * 256 + tid;
    if (tid < NDOM) {
        lcnt[tid] = 0;
        int acc = 0;
        for (int i = 0; i < NDOM; i++) { if (i == tid) soff[tid] = acc; acc += g_cnt[i]; }
    }
    __syncthreads();
    int d = dom[n];
    int rank = atomicAdd(&lcnt[d], 1);
    __syncthreads();
    if (tid < NDOM && lcnt[tid] > 0)
        lbase[tid] = soff[tid] + atomicAdd(&g_cur0[tid], lcnt[tid]);
    __syncthreads();
    g_perm[lbase[d] + rank] = n;
}

// ---------------- fused gemm1 + gemm2-partial (128x128, 4 warps, 64x64 warp tile) ----------------
__global__ __launch_bounds__(NTHR, 3) void k_gemm1(
    const float* __restrict__ W1, const float* __restrict__ b1,
    const float* __restrict__ W2, const float* __restrict__ alphas) {
    extern __shared__ char smem[];
    uint32_t sb = smem_u32(smem);
    int tid = threadIdx.x, wid = tid >> 5, lane = tid & 31;
    int d = blockIdx.z;

    int* sPerm = (int*)(smem + S_PERM);
    int* sCnt  = (int*)(smem + S_CNT);
    if (tid < NDOM) sCnt[tid] = g_cnt[tid];
    __syncthreads();
    int seg0 = 0;
#pragma unroll
    for (int i = 0; i < NDOM; i++) if (i < d) seg0 += sCnt[i];
    int seg1 = seg0 + sCnt[d];

    int row0 = seg0 + blockIdx.x * TM;
    if (row0 >= seg1) return;
    int slice = blockIdx.y;
    int colBase = slice * TN;

    if (tid < TM) {
        int r = row0 + tid;
        sPerm[tid] = (r < seg1) ? g_perm[r] : -1;
    }
    __syncthreads();

    const __half* wptr = g_w1t + ((size_t)d * HDIM + colBase) * FDIM;

    auto issue = [&](int c) {
        int k0 = c * TKC;
        uint32_t stage = sb + S_TILE + (c & 1) * S_STAGE;
#pragma unroll
        for (int i = 0; i < 8; i++) {   // A: 1024 x 16B
            int idx = i * NTHR + tid;
            int m = idx >> 3, j = idx & 7;
            int n = sPerm[m];
            const __half* src = g_f + ((n >= 0) ? ((size_t)n * FDIM + k0 + j * 8) : 0);
            uint32_t dst = stage + S_A + SWZ128((uint32_t)(m * 128 + j * 16));
            cp16(dst, src, (n >= 0) ? 16u : 0u);
        }
#pragma unroll
        for (int i = 0; i < 8; i++) {   // B: 1024 x 16B
            int idx = i * NTHR + tid;
            int nn = idx >> 3, j = idx & 7;
            const __half* src = wptr + (size_t)nn * FDIM + k0 + j * 8;
            uint32_t dst = stage + S_B + SWZ128((uint32_t)(nn * 128 + j * 16));
            cp16(dst, src, 16u);
        }
        CP_COMMIT();
    };

    int warp_m = wid & 1;      // rows warp_m*64 .. +64
    int warp_n = wid >> 1;     // cols warp_n*64 .. +64

    float acc[4][8][4];
#pragma unroll
    for (int a = 0; a < 4; a++)
#pragma unroll
        for (int b = 0; b < 8; b++)
#pragma unroll
            for (int q = 0; q < 4; q++) acc[a][b][q] = 0.f;

    uint32_t xm = (uint32_t)((lane & 7) << 4);
    uint32_t laneA = (uint32_t)((warp_m * 64 + (lane & 15)) * 128);
    uint32_t colA = (uint32_t)((lane >> 4) * 16);
    uint32_t laneB = (uint32_t)((warp_n * 64 + ((lane >> 4) << 3) + (lane & 7)) * 128);
    uint32_t colB = (uint32_t)(((lane >> 3) & 1) * 16);

    issue(0);
    issue(1);
    for (int c = 0; c < NCHUNK; c++) {
        if (c == NCHUNK - 1) { CP_WAIT(0); } else { CP_WAIT(1); }
        __syncthreads();

        uint32_t stage = sb + S_TILE + (c & 1) * S_STAGE;
        uint32_t A = stage + S_A, B = stage + S_B;

#pragma unroll
        for (int kf = 0; kf < 4; kf++) {
            uint32_t kb = (uint32_t)(kf * 32);
            uint32_t Ah[4][4];
#pragma unroll
            for (int mf = 0; mf < 4; mf++) {
                uint32_t off = laneA + (uint32_t)(mf * 2048) + ((kb + colA) ^ xm);
                ldx4(Ah[mf], A + off);
            }
            // stream B: one ldx4 (2 fragments) at a time, consume immediately
#pragma unroll
            for (int p = 0; p < 4; p++) {
                uint32_t off = laneB + (uint32_t)(p * 2048) + ((kb + colB) ^ xm);
                uint32_t q[4];
                ldx4(q, B + off);
#pragma unroll
                for (int mf = 0; mf < 4; mf++) {
                    mma16816(acc[mf][2 * p],     Ah[mf], q[0], q[1]);
                    mma16816(acc[mf][2 * p + 1], Ah[mf], q[2], q[3]);
                }
            }
        }
        __syncthreads();   // all warps done reading stage (c&1) before issue overwrites it
        if (c + 2 < NCHUNK) issue(c + 2);
    }

    // ---- stage epilogue tables (reuse stage area; mainloop fully done) ----
    float* tails = (float*)(smem + S_TILE);            // [4][128]
    float* W2s   = (float*)(smem + S_W2S);             // [128][17] alpha-prescaled
    float* dzbuf = (float*)(smem + S_DZB);             // [2 warp_n][128][16]
    {
        const float* Wd = W1 + (size_t)d * (FDIM + 3) * HDIM;
#pragma unroll
        for (int i = 0; i < 4; i++) {
            int idx = i * NTHR + tid;      // 0..511
            int r = idx >> 7, cc = idx & 127;
            tails[idx] = (r < 3) ? Wd[(size_t)(FDIM + r) * HDIM + colBase + cc]
                                 : b1[d * HDIM + colBase + cc];
        }
        float alpha = alphas[d];
        const float* W2d = W2 + (size_t)d * HDIM * KCOLS + (size_t)colBase * KCOLS;
#pragma unroll
        for (int i = 0; i < 16; i++) {
            int idx = i * NTHR + tid;      // 0..2047
            int r = idx >> 4, cc = idx & 15;
            W2s[r * 17 + cc] = W2d[r * KCOLS + cc] * alpha;
        }
    }
    __syncthreads();

    // ---- epilogue: h = relu(acc + conf-tail + bias); dz-partial = h @ W2s ----
#pragma unroll
    for (int mf = 0; mf < 4; mf++) {
        int r0 = warp_m * 64 + mf * 16 + (lane >> 2);
        int na = sPerm[r0], nb = sPerm[r0 + 8];
        float a0 = 0.f, a1 = 0.f, a2 = 0.f, c0 = 0.f, c1 = 0.f, c2 = 0.f;
        if (na >= 0) { a0 = g_conf[na * 3]; a1 = g_conf[na * 3 + 1]; a2 = g_conf[na * 3 + 2]; }
        if (nb >= 0) { c0 = g_conf[nb * 3]; c1 = g_conf[nb * 3 + 1]; c2 = g_conf[nb * 3 + 2]; }
        float dzA[KCOLS], dzB[KCOLS];
#pragma unroll
        for (int c = 0; c < KCOLS; c++) { dzA[c] = 0.f; dzB[c] = 0.f; }
#pragma unroll
        for (int nf = 0; nf < 8; nf++) {
            int col = warp_n * 64 + nf * 8 + (lane & 3) * 2;
            float t0x = tails[col],       t0y = tails[col + 1];
            float t1x = tails[128 + col], t1y = tails[128 + col + 1];
            float t2x = tails[256 + col], t2y = tails[256 + col + 1];
            float tbx = tails[384 + col], tby = tails[384 + col + 1];
            float hxA = fmaxf(acc[mf][nf][0] + a0 * t0x + a1 * t1x + a2 * t2x + tbx, 0.f);
            float hyA = fmaxf(acc[mf][nf][1] + a0 * t0y + a1 * t1y + a2 * t2y + tby, 0.f);
            float hxB = fmaxf(acc[mf][nf][2] + c0 * t0x + c1 * t1x + c2 * t2x + tbx, 0.f);
            float hyB = fmaxf(acc[mf][nf][3] + c0 * t0y + c1 * t1y + c2 * t2y + tby, 0.f);
            const float* wx = W2s + col * 17;
            const float* wy = W2s + (col + 1) * 17;
#pragma unroll
            for (int c = 0; c < KCOLS; c++) {
                dzA[c] += hxA * wx[c] + hyA * wy[c];
                dzB[c] += hxB * wx[c] + hyB * wy[c];
            }
        }
        // quad reduce over lane&3 (lanes sharing a row)
#pragma unroll
        for (int off = 1; off <= 2; off <<= 1) {
#pragma unroll
            for (int c = 0; c < KCOLS; c++) {
                dzA[c] += __shfl_xor_sync(0xffffffffu, dzA[c], off);
                dzB[c] += __shfl_xor_sync(0xffffffffu, dzB[c], off);
            }
        }
        int q = (lane & 3) * 4;
        *(float4*)(dzbuf + ((warp_n * 128 + r0) * KCOLS) + q) =
            make_float4(dzA[q], dzA[q + 1], dzA[q + 2], dzA[q + 3]);
        *(float4*)(dzbuf + ((warp_n * 128 + r0 + 8) * KCOLS) + q) =
            make_float4(dzB[q], dzB[q + 1], dzB[q + 2], dzB[q + 3]);
    }
    __syncthreads();

    // ---- deterministic cross-warp_n reduce: 512 float4 groups, 4 per thread ----
#pragma unroll
    for (int i = 0; i < 4; i++) {
        int idx = i * NTHR + tid;          // 0..511 (float4 index)
        int row = idx >> 2, q = (idx & 3) * 4;
        int n = sPerm[row];
        if (n < 0) continue;
        float4 s0 = *(float4*)(dzbuf + ((0 * 128 + row) * KCOLS) + q);
        float4 s1 = *(float4*)(dzbuf + ((1 * 128 + row) * KCOLS) + q);
        float4 r;
        r.x = s0.x + s1.x;
        r.y = s0.y + s1.y;
        r.z = s0.z + s1.z;
        r.w = s0.w + s1.w;
        *(float4*)(g_dz + ((size_t)slice * NROWS + n) * KCOLS + q) = r;
    }
}

// ---------------- final: out = z, then out[:, cols[d]] += b2*alpha + sum dz ----------------
__global__ void k_final(const float* __restrict__ z, const int* __restrict__ dom,
                        const int* __restrict__ cols, const float* __restrict__ b2,
                        const float* __restrict__ alphas, float* __restrict__ out) {
    int row = blockIdx.x * 8 + (threadIdx.x >> 5);
    int lane = threadIdx.x & 31;
    ((float4*)out)[row * 32 + lane] = ((const float4*)z)[row * 32 + lane];
    __syncwarp();
    if (lane < KCOLS) {
        int d = dom[row];
        float s = b2[d * KCOLS + lane] * alphas[d];
#pragma unroll
        for (int sl = 0; sl < NSLICE; sl++)
            s += g_dz[((size_t)sl * NROWS + row) * KCOLS + lane];
        out[row * CDIM + cols[d * KCOLS + lane]] += s;
    }
}

// ---------------- launcher ----------------
extern "C" void kernel_launch(void* const* d_in, const int* in_sizes, int n_in,
                              void* d_out, int out_size) {
    const float* z      = (const float*)d_in[0];
    const int*   dom    = (const int*)d_in[1];
    const float* feats  = (const float*)d_in[2];
    const int*   cols   = (const int*)d_in[3];
    const float* W1     = (const float*)d_in[4];
    const float* b1     = (const float*)d_in[5];
    const float* W2     = (const float*)d_in[6];
    const float* b2     = (const float*)d_in[7];
    const float* alphas = (const float*)d_in[8];
    float* out = (float*)d_out;

    cudaFuncSetAttribute(k_gemm1, cudaFuncAttributeMaxDynamicSharedMemorySize, SMEM_SZ);

    k_zero<<<1, 32>>>();
    k_prep<<<NB_CVT + NB_W1T + NB_CONF, 256>>>(feats, W1, z, dom, cols);
    k_scatter<<<NROWS / 256, 256>>>(dom);

    dim3 g1(NRT, NSLICE, NDOM);   // over-provisioned row tiles; empty ones exit
    k_gemm1<<<g1, NTHR, SMEM_SZ>>>(W1, b1, W2, alphas);

    k_final<<<NROWS / 8, 256>>>(z, dom, cols, b2, alphas, out);
}

// round 15
// speedup vs baseline: 1.1234x; 1.1234x over previous
#include <cuda_runtime.h>
#include <cuda_fp16.h>
#include <cstdint>

#define NROWS 16384
#define CDIM  128
#define FDIM  768
#define HDIM  768
#define NDOM  8
#define KCOLS 16
#define SEGCAP 4096              // fixed per-domain segment capacity

#define TM   128
#define TN   128
#define TKC  64
#define NCHUNK (FDIM / TKC)     // 12
#define NSLICE (HDIM / TN)      // 6
#define NRT   (SEGCAP / TM)     // 32 row tiles per domain

// ---------------- scratch ----------------
__device__ int    g_cnt[NDOM];
__device__ int    g_perm[NDOM * SEGCAP];
__device__ float  g_conf[NROWS * 3];
__device__ __half g_f[(size_t)NROWS * FDIM];                   // feats fp16
__device__ __half g_w1t[(size_t)NDOM * HDIM * FDIM];           // W1^T fp16 [d][n][k]
__device__ float  g_dz[(size_t)NSLICE * NROWS * KCOLS];        // partial dz per col-slice

// ---------------- helpers ----------------
__device__ __forceinline__ uint32_t smem_u32(const void* p) {
    uint32_t a;
    asm("{ .reg .u64 t; cvta.to.shared.u64 t, %1; cvt.u32.u64 %0, t; }" : "=r"(a) : "l"(p));
    return a;
}
#define SWZ128(bo) ((bo) ^ (((bo) >> 3) & 0x70))

__device__ __forceinline__ void cp16(uint32_t dst, const void* src, uint32_t sz) {
    asm volatile("cp.async.cg.shared.global [%0], [%1], 16, %2;"
                 :: "r"(dst), "l"(src), "r"(sz) : "memory");
}
#define CP_COMMIT() asm volatile("cp.async.commit_group;" ::: "memory")
#define CP_WAIT(n)  asm volatile("cp.async.wait_group %0;" :: "n"(n) : "memory")

__device__ __forceinline__ void ldx4(uint32_t r[4], uint32_t addr) {
    asm volatile("ldmatrix.sync.aligned.m8n8.x4.shared.b16 {%0,%1,%2,%3}, [%4];"
                 : "=r"(r[0]), "=r"(r[1]), "=r"(r[2]), "=r"(r[3]) : "r"(addr));
}
__device__ __forceinline__ void mma16816(float c[4], const uint32_t a[4], const uint32_t b[2]) {
    asm volatile("mma.sync.aligned.m16n8k16.row.col.f32.f16.f16.f32 "
                 "{%0,%1,%2,%3}, {%4,%5,%6,%7}, {%8,%9}, {%0,%1,%2,%3};"
                 : "+f"(c[0]), "+f"(c[1]), "+f"(c[2]), "+f"(c[3])
                 : "r"(a[0]), "r"(a[1]), "r"(a[2]), "r"(a[3]), "r"(b[0]), "r"(b[1]));
}

// ---------------- SMEM layout (gemm1): 3 stages ----------------
#define S_PERM  0            // 128 ints (512 B)
#define S_TILE  1024
#define S_STAGE 32768        // A 16KB + B 16KB
#define S_A     0
#define S_B     16384
#define S_DZB   (S_TILE + 12288)
#define SMEM_SZ (1024 + 3 * 32768)   // 99328, 2 CTAs/SM

// ---------------- k_prep: cvt feats | transpose W1 | conf + rank + perm ----------------
#define NB_CVT  (NROWS * FDIM / 4 / 256)            // 12288
#define NB_W1T  ((FDIM / 32) * (HDIM / 32) * NDOM)  // 4608
#define NB_CONF (NROWS / 256)                       // 64

__global__ void k_prep(const float* __restrict__ feats, const float* __restrict__ W1,
                       const float* __restrict__ z, const int* __restrict__ dom,
                       const int* __restrict__ cols) {
    int b = blockIdx.x;
    int tid = threadIdx.x;
    if (b < NB_CVT) {
        int i = b * 256 + tid;
        float4 v = ((const float4*)feats)[i];
        __half2* dst = (__half2*)g_f;
        dst[i * 2 + 0] = __floats2half2_rn(v.x, v.y);
        dst[i * 2 + 1] = __floats2half2_rn(v.z, v.w);
    } else if (b < NB_CVT + NB_W1T) {
        __shared__ float t[32][33];
        int bi = b - NB_CVT;
        int d = bi / ((FDIM / 32) * (HDIM / 32));
        int rem = bi % ((FDIM / 32) * (HDIM / 32));
        int k0 = (rem / (HDIM / 32)) * 32, n0 = (rem % (HDIM / 32)) * 32;
        int tx = tid & 31, ty = tid >> 5;
        const float* src = W1 + (size_t)d * (FDIM + 3) * HDIM;
#pragma unroll
        for (int r = 0; r < 4; r++)
            t[ty + 8 * r][tx] = src[(size_t)(k0 + ty + 8 * r) * HDIM + n0 + tx];
        __syncthreads();
#pragma unroll
        for (int r = 0; r < 4; r++) {
            size_t o = ((size_t)d * HDIM + n0 + ty + 8 * r) * FDIM + k0 + tx;
            g_w1t[o] = __float2half_rn(t[tx][ty + 8 * r]);
        }
    } else {
        // conf features + block-aggregated rank assignment + perm scatter
        __shared__ int lcnt[NDOM], lbase[NDOM];
        int n = (b - NB_CVT - NB_W1T) * 256 + tid;
        if (tid < NDOM) lcnt[tid] = 0;
        __syncthreads();
        int d = dom[n];
        int rank = atomicAdd(&lcnt[d], 1);
        float v[KCOLS];
#pragma unroll
        for (int i = 0; i < KCOLS; i++) v[i] = z[(size_t)n * CDIM + cols[d * KCOLS + i]];
        float m = v[0];
#pragma unroll
        for (int i = 1; i < KCOLS; i++) m = fmaxf(m, v[i]);
        float e[KCOLS], s = 0.f;
#pragma unroll
        for (int i = 0; i < KCOLS; i++) { e[i] = expf(v[i] - m); s += e[i]; }
        float t1 = -1e30f, t2 = -1e30f;
#pragma unroll
        for (int i = 0; i < KCOLS; i++) {
            float x = v[i];
            if (x > t1) { t2 = t1; t1 = x; } else if (x > t2) { t2 = x; }
        }
        float inv = 1.f / s;
        float p1 = expf(t1 - m) * inv, p2 = expf(t2 - m) * inv;
        float logZ = logf(s), ent = 0.f;
#pragma unroll
        for (int i = 0; i < KCOLS; i++) { float pi = e[i] * inv; ent -= pi * (v[i] - m - logZ); }
        ent *= (1.f / logf((float)KCOLS));
        g_conf[n * 3 + 0] = p1;
        g_conf[n * 3 + 1] = p1 - p2;
        g_conf[n * 3 + 2] = ent;
        __syncthreads();
        if (tid < NDOM && lcnt[tid] > 0)
            lbase[tid] = atomicAdd(&g_cnt[tid], lcnt[tid]);
        __syncthreads();
        int pos = lbase[d] + rank;
        if (pos < SEGCAP) g_perm[d * SEGCAP + pos] = n;
    }
}

// ---------------- fused gemm1 + gemm2-partial (128x128, 8 warps, 3-stage) ----------------
__global__ __launch_bounds__(256, 2) void k_gemm1(
    const float* __restrict__ W1, const float* __restrict__ b1,
    const float* __restrict__ W2, const float* __restrict__ alphas) {
    extern __shared__ char smem[];
    uint32_t sb = smem_u32(smem);
    int tid = threadIdx.x, wid = tid >> 5, lane = tid & 31;
    int d = blockIdx.z;

    int cnt = g_cnt[d];
    int rowT0 = blockIdx.x * TM;
    if (rowT0 >= cnt) return;
    int slice = blockIdx.y;
    int colBase = slice * TN;

    int* sPerm = (int*)(smem + S_PERM);
    if (tid < TM) {
        int r = rowT0 + tid;
        sPerm[tid] = (r < cnt) ? g_perm[d * SEGCAP + r] : -1;
    }
    __syncthreads();

    const __half* wptr = g_w1t + ((size_t)d * HDIM + colBase) * FDIM;

    auto issue = [&](int c) {
        int k0 = c * TKC;
        uint32_t stage = sb + S_TILE + (c % 3) * S_STAGE;
#pragma unroll
        for (int i = 0; i < 4; i++) {   // A: 1024 x 16B
            int idx = i * 256 + tid;
            int m = idx >> 3, j = idx & 7;
            int n = sPerm[m];
            const __half* src = g_f + ((n >= 0) ? ((size_t)n * FDIM + k0 + j * 8) : 0);
            uint32_t dst = stage + S_A + SWZ128((uint32_t)(m * 128 + j * 16));
            cp16(dst, src, (n >= 0) ? 16u : 0u);
        }
#pragma unroll
        for (int i = 0; i < 4; i++) {   // B: 1024 x 16B
            int idx = i * 256 + tid;
            int nn = idx >> 3, j = idx & 7;
            const __half* src = wptr + (size_t)nn * FDIM + k0 + j * 8;
            uint32_t dst = stage + S_B + SWZ128((uint32_t)(nn * 128 + j * 16));
            cp16(dst, src, 16u);
        }
        CP_COMMIT();
    };

    int warp_m = wid & 1;      // rows warp_m*64 .. +64
    int warp_n = wid >> 1;     // cols warp_n*32 .. +32

    float acc[4][4][4];
#pragma unroll
    for (int a = 0; a < 4; a++)
#pragma unroll
        for (int b = 0; b < 4; b++)
#pragma unroll
            for (int q = 0; q < 4; q++) acc[a][b][q] = 0.f;

    uint32_t xm = (uint32_t)((lane & 7) << 4);
    uint32_t laneA = (uint32_t)((warp_m * 64 + (lane & 15)) * 128);
    uint32_t colA = (uint32_t)((lane >> 4) * 16);
    uint32_t laneB = (uint32_t)((warp_n * 32 + ((lane >> 4) << 3) + (lane & 7)) * 128);
    uint32_t colB = (uint32_t)(((lane >> 3) & 1) * 16);

    issue(0);
    issue(1);
    for (int c = 0; c < NCHUNK; c++) {
        if (c == NCHUNK - 1) { CP_WAIT(0); } else { CP_WAIT(1); }
        // single barrier per chunk: orders stage readiness AND protects stage (c%3)
        // from being overwritten by issue(c+2) while iteration c-3 readers are active
        __syncthreads();
        if (c + 2 < NCHUNK) issue(c + 2);

        uint32_t stage = sb + S_TILE + (c % 3) * S_STAGE;
        uint32_t A = stage + S_A, B = stage + S_B;

#pragma unroll
        for (int kf = 0; kf < 4; kf++) {
            uint32_t kb = (uint32_t)(kf * 32);
            uint32_t Bh[4][2];
#pragma unroll
            for (int p = 0; p < 2; p++) {
                uint32_t off = laneB + (uint32_t)(p * 2048) + ((kb + colB) ^ xm);
                uint32_t q[4];
                ldx4(q, B + off);
                Bh[2 * p][0] = q[0]; Bh[2 * p][1] = q[1];
                Bh[2 * p + 1][0] = q[2]; Bh[2 * p + 1][1] = q[3];
            }
            uint32_t Ah[4][4];
#pragma unroll
            for (int mf = 0; mf < 4; mf++) {
                uint32_t off = laneA + (uint32_t)(mf * 2048) + ((kb + colA) ^ xm);
                ldx4(Ah[mf], A + off);
            }
#pragma unroll
            for (int mf = 0; mf < 4; mf++)
#pragma unroll
                for (int nf = 0; nf < 4; nf++)
                    mma16816(acc[mf][nf], Ah[mf], Bh[nf]);
        }
    }
    __syncthreads();   // drain all readers before epilogue smem reuse

    // ---- stage epilogue tables (reuse stage area) ----
    float* tails = (float*)(smem + S_TILE);            // [4][128]
    float* W2s   = (float*)(smem + S_TILE + 2048);     // [128][17] alpha-prescaled
    float* dzbuf = (float*)(smem + S_DZB);             // [4 warp_n][128][16]
    {
        const float* Wd = W1 + (size_t)d * (FDIM + 3) * HDIM;
#pragma unroll
        for (int i = 0; i < 2; i++) {
            int idx = i * 256 + tid;
            int r = idx >> 7, cc = idx & 127;
            tails[idx] = (r < 3) ? Wd[(size_t)(FDIM + r) * HDIM + colBase + cc]
                                 : b1[d * HDIM + colBase + cc];
        }
        float alpha = alphas[d];
        const float* W2d = W2 + (size_t)d * HDIM * KCOLS + (size_t)colBase * KCOLS;
#pragma unroll
        for (int i = 0; i < 8; i++) {
            int idx = i * 256 + tid;       // 0..2047
            int r = idx >> 4, cc = idx & 15;
            W2s[r * 17 + cc] = W2d[r * KCOLS + cc] * alpha;
        }
    }
    __syncthreads();

    // ---- epilogue: h = relu(acc + conf-tail + bias); dz-partial = h @ W2s ----
#pragma unroll
    for (int mf = 0; mf < 4; mf++) {
        int r0 = warp_m * 64 + mf * 16 + (lane >> 2);
        int na = sPerm[r0], nb = sPerm[r0 + 8];
        float a0 = 0.f, a1 = 0.f, a2 = 0.f, c0 = 0.f, c1 = 0.f, c2 = 0.f;
        if (na >= 0) { a0 = g_conf[na * 3]; a1 = g_conf[na * 3 + 1]; a2 = g_conf[na * 3 + 2]; }
        if (nb >= 0) { c0 = g_conf[nb * 3]; c1 = g_conf[nb * 3 + 1]; c2 = g_conf[nb * 3 + 2]; }
        float dzA[KCOLS], dzB[KCOLS];
#pragma unroll
        for (int c = 0; c < KCOLS; c++) { dzA[c] = 0.f; dzB[c] = 0.f; }
#pragma unroll
        for (int nf = 0; nf < 4; nf++) {
            int col = warp_n * 32 + nf * 8 + (lane & 3) * 2;
            float t0x = tails[col],       t0y = tails[col + 1];
            float t1x = tails[128 + col], t1y = tails[128 + col + 1];
            float t2x = tails[256 + col], t2y = tails[256 + col + 1];
            float tbx = tails[384 + col], tby = tails[384 + col + 1];
            float hxA = fmaxf(acc[mf][nf][0] + a0 * t0x + a1 * t1x + a2 * t2x + tbx, 0.f);
            float hyA = fmaxf(acc[mf][nf][1] + a0 * t0y + a1 * t1y + a2 * t2y + tby, 0.f);
            float hxB = fmaxf(acc[mf][nf][2] + c0 * t0x + c1 * t1x + c2 * t2x + tbx, 0.f);
            float hyB = fmaxf(acc[mf][nf][3] + c0 * t0y + c1 * t1y + c2 * t2y + tby, 0.f);
            const float* wx = W2s + col * 17;
            const float* wy = W2s + (col + 1) * 17;
#pragma unroll
            for (int c = 0; c < KCOLS; c++) {
                dzA[c] += hxA * wx[c] + hyA * wy[c];
                dzB[c] += hxB * wx[c] + hyB * wy[c];
            }
        }
        // quad reduce over lane&3 (lanes sharing a row)
#pragma unroll
        for (int off = 1; off <= 2; off <<= 1) {
#pragma unroll
            for (int c = 0; c < KCOLS; c++) {
                dzA[c] += __shfl_xor_sync(0xffffffffu, dzA[c], off);
                dzB[c] += __shfl_xor_sync(0xffffffffu, dzB[c], off);
            }
        }
        int q = (lane & 3) * 4;
        *(float4*)(dzbuf + ((warp_n * 128 + r0) * KCOLS) + q) =
            make_float4(dzA[q], dzA[q + 1], dzA[q + 2], dzA[q + 3]);
        *(float4*)(dzbuf + ((warp_n * 128 + r0 + 8) * KCOLS) + q) =
            make_float4(dzB[q], dzB[q + 1], dzB[q + 2], dzB[q + 3]);
    }
    __syncthreads();

    // ---- deterministic cross-warp_n reduce: 512 float4 groups, 2 per thread ----
#pragma unroll
    for (int i = 0; i < 2; i++) {
        int idx = i * 256 + tid;          // 0..511  (float4 index)
        int row = idx >> 2, q = (idx & 3) * 4;
        int n = sPerm[row];
        if (n < 0) continue;
        float4 s0 = *(float4*)(dzbuf + ((0 * 128 + row) * KCOLS) + q);
        float4 s1 = *(float4*)(dzbuf + ((1 * 128 + row) * KCOLS) + q);
        float4 s2 = *(float4*)(dzbuf + ((2 * 128 + row) * KCOLS) + q);
        float4 s3 = *(float4*)(dzbuf + ((3 * 128 + row) * KCOLS) + q);
        float4 r;
        r.x = (s0.x + s1.x) + (s2.x + s3.x);
        r.y = (s0.y + s1.y) + (s2.y + s3.y);
        r.z = (s0.z + s1.z) + (s2.z + s3.z);
        r.w = (s0.w + s1.w) + (s2.w + s3.w);
        *(float4*)(g_dz + ((size_t)slice * NROWS + n) * KCOLS + q) = r;
    }
}

// ---------------- final: out = z, then out[:, cols[d]] += b2*alpha + sum dz ----------------
__global__ void k_final(const float* __restrict__ z, const int* __restrict__ dom,
                        const int* __restrict__ cols, const float* __restrict__ b2,
                        const float* __restrict__ alphas, float* __restrict__ out) {
    int row = blockIdx.x * 8 + (threadIdx.x >> 5);
    int lane = threadIdx.x & 31;
    ((float4*)out)[row * 32 + lane] = ((const float4*)z)[row * 32 + lane];
    __syncwarp();
    if (lane < KCOLS) {
        int d = dom[row];
        float s = b2[d * KCOLS + lane] * alphas[d];
#pragma unroll
        for (int sl = 0; sl < NSLICE; sl++)
            s += g_dz[((size_t)sl * NROWS + row) * KCOLS + lane];
        out[row * CDIM + cols[d * KCOLS + lane]] += s;
    }
}

// ---------------- launcher ----------------
extern "C" void kernel_launch(void* const* d_in, const int* in_sizes, int n_in,
                              void* d_out, int out_size) {
    const float* z      = (const float*)d_in[0];
    const int*   dom    = (const int*)d_in[1];
    const float* feats  = (const float*)d_in[2];
    const int*   cols   = (const int*)d_in[3];
    const float* W1     = (const float*)d_in[4];
    const float* b1     = (const float*)d_in[5];
    const float* W2     = (const float*)d_in[6];
    const float* b2     = (const float*)d_in[7];
    const float* alphas = (const float*)d_in[8];
    float* out = (float*)d_out;

    cudaFuncSetAttribute(k_gemm1, cudaFuncAttributeMaxDynamicSharedMemorySize, SMEM_SZ);

    void* cntAddr = nullptr;
    cudaGetSymbolAddress(&cntAddr, g_cnt);
    cudaMemsetAsync(cntAddr, 0, NDOM * sizeof(int));

    k_prep<<<NB_CVT + NB_W1T + NB_CONF, 256>>>(feats, W1, z, dom, cols);

    dim3 g1(NRT, NSLICE, NDOM);   // over-provisioned row tiles; empty ones exit
    k_gemm1<<<g1, 256, SMEM_SZ>>>(W1, b1, W2, alphas);

    k_final<<<NROWS / 8, 256>>>(z, dom, cols, b2, alphas, out);
}

// round 16
// speedup vs baseline: 1.1666x; 1.0385x over previous
#include <cuda_runtime.h>
#include <cuda_fp16.h>
#include <cstdint>

#define NROWS 16384
#define CDIM  128
#define FDIM  768
#define HDIM  768
#define NDOM  8
#define KCOLS 16
#define SEGCAP 4096              // fixed per-domain segment capacity

#define TM   128
#define TN   128
#define TKC  64
#define NCHUNK (FDIM / TKC)     // 12
#define NSLICE (HDIM / TN)      // 6
#define NRT   (SEGCAP / TM)     // 32 row tiles per domain

// ---------------- scratch ----------------
__device__ int    g_cnt[NDOM];
__device__ int    g_perm[NDOM * SEGCAP];
__device__ float  g_conf[NROWS * 3];
__device__ __half g_f[(size_t)NROWS * FDIM];                   // feats fp16
__device__ __half g_w1t[(size_t)NDOM * HDIM * FDIM];           // W1^T fp16 [d][n][k]
__device__ float  g_dz[(size_t)NSLICE * NROWS * KCOLS];        // partial dz per col-slice

// ---------------- helpers ----------------
__device__ __forceinline__ uint32_t smem_u32(const void* p) {
    uint32_t a;
    asm("{ .reg .u64 t; cvta.to.shared.u64 t, %1; cvt.u32.u64 %0, t; }" : "=r"(a) : "l"(p));
    return a;
}
#define SWZ128(bo) ((bo) ^ (((bo) >> 3) & 0x70))

__device__ __forceinline__ void cp16(uint32_t dst, const void* src, uint32_t sz) {
    asm volatile("cp.async.cg.shared.global [%0], [%1], 16, %2;"
                 :: "r"(dst), "l"(src), "r"(sz) : "memory");
}
#define CP_COMMIT() asm volatile("cp.async.commit_group;" ::: "memory")
#define CP_WAIT(n)  asm volatile("cp.async.wait_group %0;" :: "n"(n) : "memory")

__device__ __forceinline__ void ldx4(uint32_t r[4], uint32_t addr) {
    asm volatile("ldmatrix.sync.aligned.m8n8.x4.shared.b16 {%0,%1,%2,%3}, [%4];"
                 : "=r"(r[0]), "=r"(r[1]), "=r"(r[2]), "=r"(r[3]) : "r"(addr));
}
__device__ __forceinline__ void mma16816(float c[4], const uint32_t a[4], const uint32_t b[2]) {
    asm volatile("mma.sync.aligned.m16n8k16.row.col.f32.f16.f16.f32 "
                 "{%0,%1,%2,%3}, {%4,%5,%6,%7}, {%8,%9}, {%0,%1,%2,%3};"
                 : "+f"(c[0]), "+f"(c[1]), "+f"(c[2]), "+f"(c[3])
                 : "r"(a[0]), "r"(a[1]), "r"(a[2]), "r"(a[3]), "r"(b[0]), "r"(b[1]));
}

// ---------------- SMEM layout (gemm1): 3 stages ----------------
#define S_PERM  0            // 128 ints (512 B)
#define S_TILE  1024
#define S_STAGE 32768        // A 16KB + B 16KB
#define S_A     0
#define S_B     16384
#define S_DZB   (S_TILE + 12288)
#define SMEM_SZ (1024 + 3 * 32768)   // 99328, 2 CTAs/SM

// ---------------- k_prep: cvt feats (MLP=4) | transpose W1 | conf + rank + perm ----------------
#define NB_CVT  (NROWS * FDIM / 4 / 1024)           // 3072 blocks, 4 float4/thread
#define NB_W1T  ((FDIM / 32) * (HDIM / 32) * NDOM)  // 4608
#define NB_CONF (NROWS / 256)                       // 64

__global__ void k_prep(const float* __restrict__ feats, const float* __restrict__ W1,
                       const float* __restrict__ z, const int* __restrict__ dom,
                       const int* __restrict__ cols) {
    int b = blockIdx.x;
    int tid = threadIdx.x;
    if (b < NB_CVT) {
        // 4 float4 per thread, batched loads for MLP
        float4 v[4];
        int base = b * 1024 + tid;
#pragma unroll
        for (int i = 0; i < 4; i++) v[i] = ((const float4*)feats)[base + i * 256];
        __half2* dst = (__half2*)g_f;
#pragma unroll
        for (int i = 0; i < 4; i++) {
            int o = (base + i * 256) * 2;
            dst[o + 0] = __floats2half2_rn(v[i].x, v[i].y);
            dst[o + 1] = __floats2half2_rn(v[i].z, v[i].w);
        }
    } else if (b < NB_CVT + NB_W1T) {
        __shared__ float t[32][33];
        int bi = b - NB_CVT;
        int d = bi / ((FDIM / 32) * (HDIM / 32));
        int rem = bi % ((FDIM / 32) * (HDIM / 32));
        int k0 = (rem / (HDIM / 32)) * 32, n0 = (rem % (HDIM / 32)) * 32;
        int tx = tid & 31, ty = tid >> 5;
        const float* src = W1 + (size_t)d * (FDIM + 3) * HDIM;
#pragma unroll
        for (int r = 0; r < 4; r++)
            t[ty + 8 * r][tx] = src[(size_t)(k0 + ty + 8 * r) * HDIM + n0 + tx];
        __syncthreads();
#pragma unroll
        for (int r = 0; r < 4; r++) {
            size_t o = ((size_t)d * HDIM + n0 + ty + 8 * r) * FDIM + k0 + tx;
            g_w1t[o] = __float2half_rn(t[tx][ty + 8 * r]);
        }
    } else {
        // conf features + block-aggregated rank assignment + perm scatter
        __shared__ int lcnt[NDOM], lbase[NDOM];
        int n = (b - NB_CVT - NB_W1T) * 256 + tid;
        if (tid < NDOM) lcnt[tid] = 0;
        __syncthreads();
        int d = dom[n];
        int rank = atomicAdd(&lcnt[d], 1);
        float v[KCOLS];
#pragma unroll
        for (int i = 0; i < KCOLS; i++) v[i] = z[(size_t)n * CDIM + cols[d * KCOLS + i]];
        float m = v[0];
#pragma unroll
        for (int i = 1; i < KCOLS; i++) m = fmaxf(m, v[i]);
        float e[KCOLS], s = 0.f;
#pragma unroll
        for (int i = 0; i < KCOLS; i++) { e[i] = expf(v[i] - m); s += e[i]; }
        float t1 = -1e30f, t2 = -1e30f;
#pragma unroll
        for (int i = 0; i < KCOLS; i++) {
            float x = v[i];
            if (x > t1) { t2 = t1; t1 = x; } else if (x > t2) { t2 = x; }
        }
        float inv = 1.f / s;
        float p1 = expf(t1 - m) * inv, p2 = expf(t2 - m) * inv;
        float logZ = logf(s), ent = 0.f;
#pragma unroll
        for (int i = 0; i < KCOLS; i++) { float pi = e[i] * inv; ent -= pi * (v[i] - m - logZ); }
        ent *= (1.f / logf((float)KCOLS));
        g_conf[n * 3 + 0] = p1;
        g_conf[n * 3 + 1] = p1 - p2;
        g_conf[n * 3 + 2] = ent;
        __syncthreads();
        if (tid < NDOM && lcnt[tid] > 0)
            lbase[tid] = atomicAdd(&g_cnt[tid], lcnt[tid]);
        __syncthreads();
        int pos = lbase[d] + rank;
        if (pos < SEGCAP) g_perm[d * SEGCAP + pos] = n;
    }
}

// ---------------- fused gemm1 + gemm2-partial (128x128, 8 warps, 3-stage) ----------------
// grid: (NSLICE, NRT, NDOM) — slices fastest so A tiles are L2-shared across slices
__global__ __launch_bounds__(256, 2) void k_gemm1(
    const float* __restrict__ W1, const float* __restrict__ b1,
    const float* __restrict__ W2, const float* __restrict__ alphas) {
    extern __shared__ char smem[];
    uint32_t sb = smem_u32(smem);
    int tid = threadIdx.x, wid = tid >> 5, lane = tid & 31;
    int d = blockIdx.z;

    int cnt = g_cnt[d];
    int rowT0 = blockIdx.y * TM;
    if (rowT0 >= cnt) return;
    int slice = blockIdx.x;
    int colBase = slice * TN;

    int* sPerm = (int*)(smem + S_PERM);
    if (tid < TM) {
        int r = rowT0 + tid;
        sPerm[tid] = (r < cnt) ? g_perm[d * SEGCAP + r] : -1;
    }
    __syncthreads();

    const __half* wptr = g_w1t + ((size_t)d * HDIM + colBase) * FDIM;

    auto issue = [&](int c) {
        int k0 = c * TKC;
        uint32_t stage = sb + S_TILE + (c % 3) * S_STAGE;
#pragma unroll
        for (int i = 0; i < 4; i++) {   // A: 1024 x 16B
            int idx = i * 256 + tid;
            int m = idx >> 3, j = idx & 7;
            int n = sPerm[m];
            const __half* src = g_f + ((n >= 0) ? ((size_t)n * FDIM + k0 + j * 8) : 0);
            uint32_t dst = stage + S_A + SWZ128((uint32_t)(m * 128 + j * 16));
            cp16(dst, src, (n >= 0) ? 16u : 0u);
        }
#pragma unroll
        for (int i = 0; i < 4; i++) {   // B: 1024 x 16B
            int idx = i * 256 + tid;
            int nn = idx >> 3, j = idx & 7;
            const __half* src = wptr + (size_t)nn * FDIM + k0 + j * 8;
            uint32_t dst = stage + S_B + SWZ128((uint32_t)(nn * 128 + j * 16));
            cp16(dst, src, 16u);
        }
        CP_COMMIT();
    };

    int warp_m = wid & 1;      // rows warp_m*64 .. +64
    int warp_n = wid >> 1;     // cols warp_n*32 .. +32

    float acc[4][4][4];
#pragma unroll
    for (int a = 0; a < 4; a++)
#pragma unroll
        for (int b = 0; b < 4; b++)
#pragma unroll
            for (int q = 0; q < 4; q++) acc[a][b][q] = 0.f;

    uint32_t xm = (uint32_t)((lane & 7) << 4);
    uint32_t laneA = (uint32_t)((warp_m * 64 + (lane & 15)) * 128);
    uint32_t colA = (uint32_t)((lane >> 4) * 16);
    uint32_t laneB = (uint32_t)((warp_n * 32 + ((lane >> 4) << 3) + (lane & 7)) * 128);
    uint32_t colB = (uint32_t)(((lane >> 3) & 1) * 16);

    issue(0);
    issue(1);
    for (int c = 0; c < NCHUNK; c++) {
        if (c == NCHUNK - 1) { CP_WAIT(0); } else { CP_WAIT(1); }
        // single barrier per chunk: orders stage readiness AND protects stage (c%3)
        // from being overwritten by issue(c+2) while iteration c-3 readers are active
        __syncthreads();
        if (c + 2 < NCHUNK) issue(c + 2);

        uint32_t stage = sb + S_TILE + (c % 3) * S_STAGE;
        uint32_t A = stage + S_A, B = stage + S_B;

#pragma unroll
        for (int kf = 0; kf < 4; kf++) {
            uint32_t kb = (uint32_t)(kf * 32);
            uint32_t Bh[4][2];
#pragma unroll
            for (int p = 0; p < 2; p++) {
                uint32_t off = laneB + (uint32_t)(p * 2048) + ((kb + colB) ^ xm);
                uint32_t q[4];
                ldx4(q, B + off);
                Bh[2 * p][0] = q[0]; Bh[2 * p][1] = q[1];
                Bh[2 * p + 1][0] = q[2]; Bh[2 * p + 1][1] = q[3];
            }
            uint32_t Ah[4][4];
#pragma unroll
            for (int mf = 0; mf < 4; mf++) {
                uint32_t off = laneA + (uint32_t)(mf * 2048) + ((kb + colA) ^ xm);
                ldx4(Ah[mf], A + off);
            }
#pragma unroll
            for (int mf = 0; mf < 4; mf++)
#pragma unroll
                for (int nf = 0; nf < 4; nf++)
                    mma16816(acc[mf][nf], Ah[mf], Bh[nf]);
        }
    }
    __syncthreads();   // drain all readers before epilogue smem reuse

    // ---- stage epilogue tables (reuse stage area) ----
    float* tails = (float*)(smem + S_TILE);            // [4][128]
    float* W2s   = (float*)(smem + S_TILE + 2048);     // [128][17] alpha-prescaled
    float* dzbuf = (float*)(smem + S_DZB);             // [4 warp_n][128][16]
    {
        const float* Wd = W1 + (size_t)d * (FDIM + 3) * HDIM;
#pragma unroll
        for (int i = 0; i < 2; i++) {
            int idx = i * 256 + tid;
            int r = idx >> 7, cc = idx & 127;
            tails[idx] = (r < 3) ? Wd[(size_t)(FDIM + r) * HDIM + colBase + cc]
                                 : b1[d * HDIM + colBase + cc];
        }
        float alpha = alphas[d];
        const float* W2d = W2 + (size_t)d * HDIM * KCOLS + (size_t)colBase * KCOLS;
#pragma unroll
        for (int i = 0; i < 8; i++) {
            int idx = i * 256 + tid;       // 0..2047
            int r = idx >> 4, cc = idx & 15;
            W2s[r * 17 + cc] = W2d[r * KCOLS + cc] * alpha;
        }
    }
    __syncthreads();

    // ---- epilogue: h = relu(acc + conf-tail + bias); dz-partial = h @ W2s ----
#pragma unroll
    for (int mf = 0; mf < 4; mf++) {
        int r0 = warp_m * 64 + mf * 16 + (lane >> 2);
        int na = sPerm[r0], nb = sPerm[r0 + 8];
        float a0 = 0.f, a1 = 0.f, a2 = 0.f, c0 = 0.f, c1 = 0.f, c2 = 0.f;
        if (na >= 0) { a0 = g_conf[na * 3]; a1 = g_conf[na * 3 + 1]; a2 = g_conf[na * 3 + 2]; }
        if (nb >= 0) { c0 = g_conf[nb * 3]; c1 = g_conf[nb * 3 + 1]; c2 = g_conf[nb * 3 + 2]; }
        float dzA[KCOLS], dzB[KCOLS];
#pragma unroll
        for (int c = 0; c < KCOLS; c++) { dzA[c] = 0.f; dzB[c] = 0.f; }
#pragma unroll
        for (int nf = 0; nf < 4; nf++) {
            int col = warp_n * 32 + nf * 8 + (lane & 3) * 2;
            float t0x = tails[col],       t0y = tails[col + 1];
            float t1x = tails[128 + col], t1y = tails[128 + col + 1];
            float t2x = tails[256 + col], t2y = tails[256 + col + 1];
            float tbx = tails[384 + col], tby = tails[384 + col + 1];
            float hxA = fmaxf(acc[mf][nf][0] + a0 * t0x + a1 * t1x + a2 * t2x + tbx, 0.f);
            float hyA = fmaxf(acc[mf][nf][1] + a0 * t0y + a1 * t1y + a2 * t2y + tby, 0.f);
            float hxB = fmaxf(acc[mf][nf][2] + c0 * t0x + c1 * t1x + c2 * t2x + tbx, 0.f);
            float hyB = fmaxf(acc[mf][nf][3] + c0 * t0y + c1 * t1y + c2 * t2y + tby, 0.f);
            const float* wx = W2s + col * 17;
            const float* wy = W2s + (col + 1) * 17;
#pragma unroll
            for (int c = 0; c < KCOLS; c++) {
                dzA[c] += hxA * wx[c] + hyA * wy[c];
                dzB[c] += hxB * wx[c] + hyB * wy[c];
            }
        }
        // quad reduce over lane&3 (lanes sharing a row)
#pragma unroll
        for (int off = 1; off <= 2; off <<= 1) {
#pragma unroll
            for (int c = 0; c < KCOLS; c++) {
                dzA[c] += __shfl_xor_sync(0xffffffffu, dzA[c], off);
                dzB[c] += __shfl_xor_sync(0xffffffffu, dzB[c], off);
            }
        }
        int q = (lane & 3) * 4;
        *(float4*)(dzbuf + ((warp_n * 128 + r0) * KCOLS) + q) =
            make_float4(dzA[q], dzA[q + 1], dzA[q + 2], dzA[q + 3]);
        *(float4*)(dzbuf + ((warp_n * 128 + r0 + 8) * KCOLS) + q) =
            make_float4(dzB[q], dzB[q + 1], dzB[q + 2], dzB[q + 3]);
    }
    __syncthreads();

    // ---- deterministic cross-warp_n reduce: 512 float4 groups, 2 per thread ----
#pragma unroll
    for (int i = 0; i < 2; i++) {
        int idx = i * 256 + tid;          // 0..511  (float4 index)
        int row = idx >> 2, q = (idx & 3) * 4;
        int n = sPerm[row];
        if (n < 0) continue;
        float4 s0 = *(float4*)(dzbuf + ((0 * 128 + row) * KCOLS) + q);
        float4 s1 = *(float4*)(dzbuf + ((1 * 128 + row) * KCOLS) + q);
        float4 s2 = *(float4*)(dzbuf + ((2 * 128 + row) * KCOLS) + q);
        float4 s3 = *(float4*)(dzbuf + ((3 * 128 + row) * KCOLS) + q);
        float4 r;
        r.x = (s0.x + s1.x) + (s2.x + s3.x);
        r.y = (s0.y + s1.y) + (s2.y + s3.y);
        r.z = (s0.z + s1.z) + (s2.z + s3.z);
        r.w = (s0.w + s1.w) + (s2.w + s3.w);
        *(float4*)(g_dz + ((size_t)slice * NROWS + n) * KCOLS + q) = r;
    }
}

// ---------------- final: out = z, then out[:, cols[d]] += b2*alpha + sum dz ----------------
__global__ void k_final(const float* __restrict__ z, const int* __restrict__ dom,
                        const int* __restrict__ cols, const float* __restrict__ b2,
                        const float* __restrict__ alphas, float* __restrict__ out) {
    int row = blockIdx.x * 8 + (threadIdx.x >> 5);
    int lane = threadIdx.x & 31;
    ((float4*)out)[row * 32 + lane] = ((const float4*)z)[row * 32 + lane];
    __syncwarp();
    if (lane < KCOLS) {
        int d = dom[row];
        float s = b2[d * KCOLS + lane] * alphas[d];
#pragma unroll
        for (int sl = 0; sl < NSLICE; sl++)
            s += g_dz[((size_t)sl * NROWS + row) * KCOLS + lane];
        out[row * CDIM + cols[d * KCOLS + lane]] += s;
    }
}

// ---------------- launcher ----------------
extern "C" void kernel_launch(void* const* d_in, const int* in_sizes, int n_in,
                              void* d_out, int out_size) {
    const float* z      = (const float*)d_in[0];
    const int*   dom    = (const int*)d_in[1];
    const float* feats  = (const float*)d_in[2];
    const int*   cols   = (const int*)d_in[3];
    const float* W1     = (const float*)d_in[4];
    const float* b1     = (const float*)d_in[5];
    const float* W2     = (const float*)d_in[6];
    const float* b2     = (const float*)d_in[7];
    const float* alphas = (const float*)d_in[8];
    float* out = (float*)d_out;

    cudaFuncSetAttribute(k_gemm1, cudaFuncAttributeMaxDynamicSharedMemorySize, SMEM_SZ);

    void* cntAddr = nullptr;
    cudaGetSymbolAddress(&cntAddr, g_cnt);
    cudaMemsetAsync(cntAddr, 0, NDOM * sizeof(int));

    k_prep<<<NB_CVT + NB_W1T + NB_CONF, 256>>>(feats, W1, z, dom, cols);

    dim3 g1(NSLICE, NRT, NDOM);   // slices fastest; over-provisioned row tiles exit
    k_gemm1<<<g1, 256, SMEM_SZ>>>(W1, b1, W2, alphas);

    k_final<<<NROWS / 8, 256>>>(z, dom, cols, b2, alphas, out);
}